// round 11
// baseline (speedup 1.0000x reference)
#include <cuda_runtime.h>
#include <math.h>

#define WSTR 1048
#define HSTR 1028
#define GRU_SMEM ((24*WSTR + 8*HSTR + 256)*4)

__device__ float d_xg[12582912];    // (8,512,3072)
__device__ float d_ys[4194304];     // (8,512,1024)
__device__ float d_hbuf[2*8192];
__device__ float d_pre[33554432];   // reused pconv output
__device__ float d_dec3[8388608];   // (8,128,512,16)
__device__ float d_dec2[16777216];  // (8,128,512,32)
__device__ float d_dec1[33554432];  // (8,128,512,64)
__device__ unsigned g_bar;

__global__ void reset_bar_kernel() { g_bar = 0u; }

// C[m,n] = sum_k A[m,k]*Bm[n,k] + bias[n];  A:(4096,1024) Bm:(3072,1024)
__global__ void __launch_bounds__(256) xg_gemm_kernel(
    const float* __restrict__ A, const float* __restrict__ Bm,
    const float* __restrict__ bias, float* __restrict__ C)
{
    __shared__ float As[8][128];
    __shared__ float Bs[8][128];
    const int tid = threadIdx.x;
    const int bm = blockIdx.y * 128, bn = blockIdx.x * 128;
    const int lr = tid >> 1, lk = (tid & 1) * 4;
    const float* Ap = A  + (size_t)(bm + lr) * 1024 + lk;
    const float* Bp = Bm + (size_t)(bn + lr) * 1024 + lk;
    const int ty = tid >> 4, tx = tid & 15;
    float acc[8][8];
#pragma unroll
    for (int i = 0; i < 8; i++)
#pragma unroll
        for (int j = 0; j < 8; j++) acc[i][j] = 0.f;
    for (int k0 = 0; k0 < 1024; k0 += 8) {
        float4 a4 = *(const float4*)(Ap + k0);
        float4 b4 = *(const float4*)(Bp + k0);
        __syncthreads();
        As[lk+0][lr]=a4.x; As[lk+1][lr]=a4.y; As[lk+2][lr]=a4.z; As[lk+3][lr]=a4.w;
        Bs[lk+0][lr]=b4.x; Bs[lk+1][lr]=b4.y; Bs[lk+2][lr]=b4.z; Bs[lk+3][lr]=b4.w;
        __syncthreads();
#pragma unroll
        for (int k = 0; k < 8; k++) {
            float ar[8], br[8];
            *(float4*)(ar)   = *(const float4*)&As[k][ty*8];
            *(float4*)(ar+4) = *(const float4*)&As[k][ty*8+4];
            *(float4*)(br)   = *(const float4*)&Bs[k][tx*8];
            *(float4*)(br+4) = *(const float4*)&Bs[k][tx*8+4];
#pragma unroll
            for (int i = 0; i < 8; i++)
#pragma unroll
                for (int j = 0; j < 8; j++)
                    acc[i][j] = fmaf(ar[i], br[j], acc[i][j]);
        }
    }
#pragma unroll
    for (int i = 0; i < 8; i++) {
        int m = bm + ty*8 + i;
#pragma unroll
        for (int j = 0; j < 8; j++) {
            int n = bn + tx*8 + j;
            C[(size_t)m*3072 + n] = acc[i][j] + bias[n];
        }
    }
}

// Persistent GRU scan: 128 blocks x 192 thr, block owns 8 hidden units.
__global__ void __launch_bounds__(192) gru_scan_kernel(
    const float* __restrict__ Whh, const float* __restrict__ bhh,
    const float* __restrict__ h0, float* __restrict__ hbuf,
    float* __restrict__ ys, const float* __restrict__ xg,
    float* __restrict__ hT)
{
    extern __shared__ float sm[];
    float* Ws = sm;
    float* hs = sm + 24*WSTR;
    float* hg = hs + 8*HSTR;
    const int tid = threadIdx.x;
    const int j0 = blockIdx.x * 8;

    for (int idx = tid; idx < 24*256; idx += 192) {
        int lrr = idx >> 8, k4 = idx & 255;
        int grow = ((lrr >> 3) << 10) + j0 + (lrr & 7);
        float4 v = *(const float4*)(Whh + (size_t)grow*1024 + k4*4);
        *(float4*)&Ws[lrr*WSTR + k4*4] = v;
    }
    const int lr = tid >> 3;   // 0..23 gate-row
    const int bb = tid & 7;    // batch
    const int grow = ((lr >> 3) << 10) + j0 + (lr & 7);
    const float bh = bhh[grow];
    const float4* wp = (const float4*)(Ws + lr*WSTR);
    const float4* hp = (const float4*)(hs + bb*HSTR);
    __syncthreads();

    for (int t = 0; t < 512; t++) {
        const float* hsrc = (t == 0) ? h0 : (hbuf + (size_t)(t & 1) * 8192);
        for (int idx = tid; idx < 2048; idx += 192) {
            int b = idx >> 8, k4 = idx & 255;
            float4 v = __ldcg((const float4*)(hsrc + (size_t)b*1024) + k4);
            *(float4*)&hs[b*HSTR + k4*4] = v;
        }
        __syncthreads();

        float a0=0.f, a1=0.f, a2=0.f, a3=0.f;
#pragma unroll 8
        for (int k = 0; k < 256; k++) {
            float4 w4 = wp[k];
            float4 h4 = hp[k];
            a0 = fmaf(w4.x, h4.x, a0);
            a1 = fmaf(w4.y, h4.y, a1);
            a2 = fmaf(w4.z, h4.z, a2);
            a3 = fmaf(w4.w, h4.w, a3);
        }
        hg[lr*8 + bb] = (a0+a1) + (a2+a3) + bh;
        __syncthreads();

        if (tid < 64) {
            int jj = tid >> 3, b = tid & 7;
            int j = j0 + jj;
            float hr = hg[jj*8 + b];
            float hz = hg[(8+jj)*8 + b];
            float hn = hg[(16+jj)*8 + b];
            const float* xb = xg + (size_t)(b*512 + t)*3072 + j;
            float r = 1.f/(1.f + expf(-(xb[0]    + hr)));
            float z = 1.f/(1.f + expf(-(xb[1024] + hz)));
            float n = tanhf(xb[2048] + r*hn);
            float hnew = (1.f - z)*n + z*hs[b*HSTR + j];
            hbuf[(size_t)((t+1) & 1)*8192 + b*1024 + j] = hnew;
            ys[(size_t)(b*512 + t)*1024 + j] = hnew;
            if (t == 511) hT[b*1024 + j] = hnew;
        }
        __threadfence();
        __syncthreads();
        if (tid == 0) {
            atomicAdd(&g_bar, 1u);
            unsigned want = (unsigned)(t + 1) * gridDim.x;
            while (*((volatile unsigned*)&g_bar) < want) { }
            __threadfence();
        }
        __syncthreads();
    }
}

// out[b,c,p] = sum_k W[c,k]*X[b,k,p] + bias[c] + add ; addmode1 = emb2(ys)
__global__ void __launch_bounds__(256) pconv_kernel(
    const float* __restrict__ X, const float* __restrict__ W,
    const float* __restrict__ bias, const float* __restrict__ add,
    float* __restrict__ out, int npos, int addmode)
{
    __shared__ float Wt[32][132];
    __shared__ float Xs[32][132];
    const int tid = threadIdx.x;
    const int b = blockIdx.y, p0 = blockIdx.x * 128;
    const int ty = tid >> 4, tx = tid & 15;
    const float* Xb = X + (size_t)b * 128 * npos;
    float acc[8][8];
#pragma unroll
    for (int i = 0; i < 8; i++)
#pragma unroll
        for (int j = 0; j < 8; j++) acc[i][j] = 0.f;
    for (int k0 = 0; k0 < 128; k0 += 32) {
        __syncthreads();
#pragma unroll
        for (int l = 0; l < 4; l++) {
            int idx = tid + l*256;
            int c = idx >> 3, k4 = idx & 7;
            float4 v = *(const float4*)(W + c*128 + k0 + k4*4);
            Wt[k4*4+0][c]=v.x; Wt[k4*4+1][c]=v.y; Wt[k4*4+2][c]=v.z; Wt[k4*4+3][c]=v.w;
        }
#pragma unroll
        for (int l = 0; l < 4; l++) {
            int idx = tid + l*256;
            int k = idx >> 5, p4 = idx & 31;
            float4 v = *(const float4*)(Xb + (size_t)(k0+k)*npos + p0 + p4*4);
            *(float4*)&Xs[k][p4*4] = v;
        }
        __syncthreads();
#pragma unroll
        for (int k = 0; k < 32; k++) {
            float ar[8], br[8];
            *(float4*)(ar)   = *(const float4*)&Wt[k][ty*8];
            *(float4*)(ar+4) = *(const float4*)&Wt[k][ty*8+4];
            *(float4*)(br)   = *(const float4*)&Xs[k][tx*8];
            *(float4*)(br+4) = *(const float4*)&Xs[k][tx*8+4];
#pragma unroll
            for (int i = 0; i < 8; i++)
#pragma unroll
                for (int j = 0; j < 8; j++)
                    acc[i][j] = fmaf(ar[i], br[j], acc[i][j]);
        }
    }
#pragma unroll
    for (int i = 0; i < 8; i++) {
        int c = ty*8 + i;
        float bv = bias[c];
#pragma unroll
        for (int j = 0; j < 8; j++) {
            int p = p0 + tx*8 + j;
            float v = acc[i][j] + bv;
            if (addmode == 1) {
                int t = p >> 3, f = p & 7;
                v += add[(size_t)(b*512 + t)*1024 + f*128 + c];
            } else {
                v += add[((size_t)b*128 + c)*npos + p];
            }
            out[((size_t)b*128 + c)*npos + p] = v;
        }
    }
}

// y[b,c,t,2*fi] = relu(bias + sum_k w[c,k,1]*X[b,k,t,fi])
__global__ void __launch_bounds__(256) convt_even_kernel(
    const float* __restrict__ X, const float* __restrict__ wt,
    const float* __restrict__ bias, float* __restrict__ out,
    int npos, int fsh)
{
    __shared__ float Wt[32][132];
    __shared__ float Xs[32][132];
    const int tid = threadIdx.x;
    const int b = blockIdx.y, p0 = blockIdx.x * 128;
    const int ty = tid >> 4, tx = tid & 15;
    const int fmask = (1 << fsh) - 1;
    const float* Xb = X + (size_t)b * 128 * npos;
    float acc[8][8];
#pragma unroll
    for (int i = 0; i < 8; i++)
#pragma unroll
        for (int j = 0; j < 8; j++) acc[i][j] = 0.f;
    for (int k0 = 0; k0 < 128; k0 += 32) {
        __syncthreads();
        for (int idx = tid; idx < 4096; idx += 256) {
            int c = idx >> 5, k = idx & 31;
            Wt[k][c] = wt[(c*128 + k0 + k)*3 + 1];
        }
#pragma unroll
        for (int l = 0; l < 4; l++) {
            int idx = tid + l*256;
            int k = idx >> 5, p4 = idx & 31;
            float4 v = *(const float4*)(Xb + (size_t)(k0+k)*npos + p0 + p4*4);
            *(float4*)&Xs[k][p4*4] = v;
        }
        __syncthreads();
#pragma unroll
        for (int k = 0; k < 32; k++) {
            float ar[8], br[8];
            *(float4*)(ar)   = *(const float4*)&Wt[k][ty*8];
            *(float4*)(ar+4) = *(const float4*)&Wt[k][ty*8+4];
            *(float4*)(br)   = *(const float4*)&Xs[k][tx*8];
            *(float4*)(br+4) = *(const float4*)&Xs[k][tx*8+4];
#pragma unroll
            for (int i = 0; i < 8; i++)
#pragma unroll
                for (int j = 0; j < 8; j++)
                    acc[i][j] = fmaf(ar[i], br[j], acc[i][j]);
        }
    }
#pragma unroll
    for (int i = 0; i < 8; i++) {
        int c = ty*8 + i;
        float bv = bias[c];
#pragma unroll
        for (int j = 0; j < 8; j++) {
            int p = p0 + tx*8 + j;
            int t = p >> fsh, fi = p & fmask;
            float v = acc[i][j] + bv;
            v = (v > 0.f) ? v : 0.f;
            out[((((size_t)b*128 + c)*512 + t) << (fsh+1)) + 2*fi] = v;
        }
    }
}

// y[b,c,t,2*fi+1] = relu(bias + sum_k w[c,k,0]*X[k,t,fi] + w[c,k,2]*X[k,t,fi+1])
__global__ void __launch_bounds__(256) convt_odd_kernel(
    const float* __restrict__ X, const float* __restrict__ wt,
    const float* __restrict__ bias, float* __restrict__ out,
    int npos, int fsh)
{
    __shared__ float Wt[32][132];
    __shared__ float Xs[32][132];
    const int tid = threadIdx.x;
    const int b = blockIdx.y, p0 = blockIdx.x * 128;
    const int ty = tid >> 4, tx = tid & 15;
    const int fmask = (1 << fsh) - 1;
    const float* Xb = X + (size_t)b * 128 * npos;
    float acc[8][8];
#pragma unroll
    for (int i = 0; i < 8; i++)
#pragma unroll
        for (int j = 0; j < 8; j++) acc[i][j] = 0.f;
    for (int tap = 0; tap < 2; tap++) {
        const int widx = tap * 2;
        for (int k0 = 0; k0 < 128; k0 += 32) {
            __syncthreads();
            for (int idx = tid; idx < 4096; idx += 256) {
                int c = idx >> 5, k = idx & 31;
                Wt[k][c] = wt[(c*128 + k0 + k)*3 + widx];
            }
            for (int idx = tid; idx < 1024; idx += 256) {
                int k = idx >> 5, p4 = idx & 31;
                float vv[4];
#pragma unroll
                for (int e = 0; e < 4; e++) {
                    int p = p0 + p4*4 + e;
                    bool ok = (tap == 0) || ((p & fmask) != fmask);
                    vv[e] = ok ? Xb[(size_t)(k0+k)*npos + p + tap] : 0.f;
                }
                Xs[k][p4*4+0]=vv[0]; Xs[k][p4*4+1]=vv[1];
                Xs[k][p4*4+2]=vv[2]; Xs[k][p4*4+3]=vv[3];
            }
            __syncthreads();
#pragma unroll
            for (int k = 0; k < 32; k++) {
                float ar[8], br[8];
                *(float4*)(ar)   = *(const float4*)&Wt[k][ty*8];
                *(float4*)(ar+4) = *(const float4*)&Wt[k][ty*8+4];
                *(float4*)(br)   = *(const float4*)&Xs[k][tx*8];
                *(float4*)(br+4) = *(const float4*)&Xs[k][tx*8+4];
#pragma unroll
                for (int i = 0; i < 8; i++)
#pragma unroll
                    for (int j = 0; j < 8; j++)
                        acc[i][j] = fmaf(ar[i], br[j], acc[i][j]);
            }
        }
    }
#pragma unroll
    for (int i = 0; i < 8; i++) {
        int c = ty*8 + i;
        float bv = bias[c];
#pragma unroll
        for (int j = 0; j < 8; j++) {
            int p = p0 + tx*8 + j;
            int t = p >> fsh, fi = p & fmask;
            float v = acc[i][j] + bv;
            v = (v > 0.f) ? v : 0.f;
            out[((((size_t)b*128 + c)*512 + t) << (fsh+1)) + 2*fi + 1] = v;
        }
    }
}

// final 1x3 conv over f (C=128 -> 1) + sigmoid, one block per (b,t)
__global__ void __launch_bounds__(128) mask_kernel(
    const float* __restrict__ pre, const float* __restrict__ w0o,
    const float* __restrict__ b0o, float* __restrict__ out)
{
    __shared__ float ps[128][68];
    __shared__ float ws[384];
    const int bt = blockIdx.x;
    const int b = bt >> 9, t = bt & 511;
    const int tid = threadIdx.x;
    const float* src = pre + (((size_t)b*128 + tid)*512 + t)*64;
#pragma unroll
    for (int q = 0; q < 16; q++)
        *(float4*)&ps[tid][q*4] = ((const float4*)src)[q];
    for (int i = tid; i < 384; i += 128) ws[i] = w0o[i];
    __syncthreads();
    if (tid < 64) {
        int f = tid;
        float acc = b0o[0];
#pragma unroll 8
        for (int ci = 0; ci < 128; ci++) {
            float xm1 = (f > 0)  ? ps[ci][f-1] : 0.f;
            float x0  = ps[ci][f];
            float xp1 = (f < 63) ? ps[ci][f+1] : 0.f;
            acc += ws[ci*3+0]*xm1 + ws[ci*3+1]*x0 + ws[ci*3+2]*xp1;
        }
        out[(size_t)(b*512 + t)*64 + f] = 1.f/(1.f + expf(-acc));
    }
}

extern "C" void kernel_launch(void* const* d_in, const int* in_sizes, int n_in,
                              void* d_out, int out_size)
{
    const float* emb  = (const float*)d_in[0];
    const float* e3   = (const float*)d_in[1];
    const float* e2   = (const float*)d_in[2];
    const float* e1   = (const float*)d_in[3];
    const float* e0   = (const float*)d_in[4];
    const float* herb = (const float*)d_in[5];
    const float* Wih  = (const float*)d_in[6];
    const float* Whh  = (const float*)d_in[7];
    const float* bih  = (const float*)d_in[8];
    const float* bhh  = (const float*)d_in[9];
    const float* w3p  = (const float*)d_in[10];
    const float* b3p  = (const float*)d_in[11];
    const float* w2p  = (const float*)d_in[12];
    const float* b2p  = (const float*)d_in[13];
    const float* w1p  = (const float*)d_in[14];
    const float* b1p  = (const float*)d_in[15];
    const float* w0p  = (const float*)d_in[16];
    const float* b0p  = (const float*)d_in[17];
    const float* wt3  = (const float*)d_in[18];
    const float* bt3  = (const float*)d_in[19];
    const float* wt2  = (const float*)d_in[20];
    const float* bt2  = (const float*)d_in[21];
    const float* wt1  = (const float*)d_in[22];
    const float* bt1  = (const float*)d_in[23];
    const float* w0o  = (const float*)d_in[24];
    const float* b0o  = (const float*)d_in[25];
    float* out = (float*)d_out;

    float *xg, *ys, *hbuf, *pre, *dec3, *dec2, *dec1;
    cudaGetSymbolAddress((void**)&xg,   d_xg);
    cudaGetSymbolAddress((void**)&ys,   d_ys);
    cudaGetSymbolAddress((void**)&hbuf, d_hbuf);
    cudaGetSymbolAddress((void**)&pre,  d_pre);
    cudaGetSymbolAddress((void**)&dec3, d_dec3);
    cudaGetSymbolAddress((void**)&dec2, d_dec2);
    cudaGetSymbolAddress((void**)&dec1, d_dec1);

    static int smem_set = 0;
    if (!smem_set) {
        cudaFuncSetAttribute(gru_scan_kernel,
            cudaFuncAttributeMaxDynamicSharedMemorySize, GRU_SMEM);
        smem_set = 1;
    }

    reset_bar_kernel<<<1, 1>>>();
    xg_gemm_kernel<<<dim3(24, 32), 256>>>(emb, Wih, bih, xg);
    gru_scan_kernel<<<128, 192, GRU_SMEM>>>(Whh, bhh, herb, hbuf, ys, xg,
                                            out + 262144);
    // stage 3: f 8 -> 16
    pconv_kernel<<<dim3(32, 8), 256>>>(e3, w3p, b3p, ys, pre, 4096, 1);
    convt_even_kernel<<<dim3(32, 8), 256>>>(pre, wt3, bt3, dec3, 4096, 3);
    convt_odd_kernel <<<dim3(32, 8), 256>>>(pre, wt3, bt3, dec3, 4096, 3);
    // stage 2: f 16 -> 32
    pconv_kernel<<<dim3(64, 8), 256>>>(e2, w2p, b2p, dec3, pre, 8192, 0);
    convt_even_kernel<<<dim3(64, 8), 256>>>(pre, wt2, bt2, dec2, 8192, 4);
    convt_odd_kernel <<<dim3(64, 8), 256>>>(pre, wt2, bt2, dec2, 8192, 4);
    // stage 1: f 32 -> 64
    pconv_kernel<<<dim3(128, 8), 256>>>(e1, w1p, b1p, dec2, pre, 16384, 0);
    convt_even_kernel<<<dim3(128, 8), 256>>>(pre, wt1, bt1, dec1, 16384, 5);
    convt_odd_kernel <<<dim3(128, 8), 256>>>(pre, wt1, bt1, dec1, 16384, 5);
    // stage 0: pconv + skip, then 1x3 conv + sigmoid
    pconv_kernel<<<dim3(256, 8), 256>>>(e0, w0p, b0p, dec1, pre, 32768, 0);
    mask_kernel<<<4096, 128>>>(pre, w0o, b0o, out);
}

// round 12
// speedup vs baseline: 1.3265x; 1.3265x over previous
#include <cuda_runtime.h>
#include <math.h>

#define WSTR 1048
#define HSTR 1028
#define GRU_SMEM ((24*WSTR + 8*HSTR + 384)*4)

__device__ float d_xg[12582912];    // (8,512,3072)
__device__ float d_ys[4194304];     // (8,512,1024)
__device__ float d_hbuf[2*8192];
__device__ float d_pre[33554432];   // reused pconv output
__device__ float d_dec3[8388608];   // (8,128,512,16)
__device__ float d_dec2[16777216];  // (8,128,512,32)
__device__ float d_dec1[33554432];  // (8,128,512,64)
__device__ unsigned g_bar;

__global__ void reset_bar_kernel() { g_bar = 0u; }

// C[m,n] = sum_k A[m,k]*Bm[n,k] + bias[n];  A:(4096,1024) Bm:(3072,1024)
__global__ void __launch_bounds__(256) xg_gemm_kernel(
    const float* __restrict__ A, const float* __restrict__ Bm,
    const float* __restrict__ bias, float* __restrict__ C)
{
    __shared__ float As[8][128];
    __shared__ float Bs[8][128];
    const int tid = threadIdx.x;
    const int bm = blockIdx.y * 128, bn = blockIdx.x * 128;
    const int lr = tid >> 1, lk = (tid & 1) * 4;
    const float* Ap = A  + (size_t)(bm + lr) * 1024 + lk;
    const float* Bp = Bm + (size_t)(bn + lr) * 1024 + lk;
    const int ty = tid >> 4, tx = tid & 15;
    float acc[8][8];
#pragma unroll
    for (int i = 0; i < 8; i++)
#pragma unroll
        for (int j = 0; j < 8; j++) acc[i][j] = 0.f;

    float4 a4 = *(const float4*)(Ap);
    float4 b4 = *(const float4*)(Bp);
    for (int k0 = 0; k0 < 1024; k0 += 8) {
        __syncthreads();
        As[lk+0][lr]=a4.x; As[lk+1][lr]=a4.y; As[lk+2][lr]=a4.z; As[lk+3][lr]=a4.w;
        Bs[lk+0][lr]=b4.x; Bs[lk+1][lr]=b4.y; Bs[lk+2][lr]=b4.z; Bs[lk+3][lr]=b4.w;
        __syncthreads();
        if (k0 + 8 < 1024) {
            a4 = *(const float4*)(Ap + k0 + 8);
            b4 = *(const float4*)(Bp + k0 + 8);
        }
#pragma unroll
        for (int k = 0; k < 8; k++) {
            float ar[8], br[8];
            *(float4*)(ar)   = *(const float4*)&As[k][ty*8];
            *(float4*)(ar+4) = *(const float4*)&As[k][ty*8+4];
            *(float4*)(br)   = *(const float4*)&Bs[k][tx*8];
            *(float4*)(br+4) = *(const float4*)&Bs[k][tx*8+4];
#pragma unroll
            for (int i = 0; i < 8; i++)
#pragma unroll
                for (int j = 0; j < 8; j++)
                    acc[i][j] = fmaf(ar[i], br[j], acc[i][j]);
        }
    }
#pragma unroll
    for (int i = 0; i < 8; i++) {
        int m = bm + ty*8 + i;
#pragma unroll
        for (int j = 0; j < 8; j++) {
            int n = bn + tx*8 + j;
            C[(size_t)m*3072 + n] = acc[i][j] + bias[n];
        }
    }
}

// Persistent GRU scan: 128 blocks x 384 thr, block owns 8 hidden units.
// Split-K x2: thread (h2, lr, bb) computes half the dot for gate-row lr, batch bb.
__global__ void __launch_bounds__(384) gru_scan_kernel(
    const float* __restrict__ Whh, const float* __restrict__ bhh,
    const float* __restrict__ h0, float* __restrict__ hbuf,
    float* __restrict__ ys, const float* __restrict__ xg,
    float* __restrict__ hT)
{
    extern __shared__ float sm[];
    float* Ws   = sm;                 // 24 rows x WSTR
    float* hs   = sm + 24*WSTR;       // 8 rows x HSTR
    float* part = hs + 8*HSTR;        // 384 partials
    const int tid = threadIdx.x;
    const int j0 = blockIdx.x * 8;

    // Load this block's 24 Whh rows into smem
    for (int idx = tid; idx < 24*256; idx += 384) {
        int lrr = idx >> 8, k4 = idx & 255;
        int grow = ((lrr >> 3) << 10) + j0 + (lrr & 7);
        float4 v = *(const float4*)(Whh + (size_t)grow*1024 + k4*4);
        *(float4*)&Ws[lrr*WSTR + k4*4] = v;
    }
    const int h2 = tid / 192;
    const int r  = tid % 192;
    const int lr = r >> 3;     // 0..23 gate-row
    const int bb = r & 7;      // batch
    const float4* wp = (const float4*)(Ws + lr*WSTR + h2*512);
    const float4* hp = (const float4*)(hs + bb*HSTR + h2*512);

    // gate threads (tid<64): jj = tid>>3, b = tid&7
    float bhr = 0.f, bhz = 0.f, bhn = 0.f;
    const float* xgbase = 0;
    int jg = 0, bg = 0;
    if (tid < 64) {
        jg = j0 + (tid >> 3);
        bg = tid & 7;
        bhr = bhh[jg];
        bhz = bhh[1024 + jg];
        bhn = bhh[2048 + jg];
        xgbase = xg + (size_t)bg * 512 * 3072 + jg;
    }
    __syncthreads();

    for (int t = 0; t < 512; t++) {
        // stage h_t into smem
        const float* hsrc = (t == 0) ? h0 : (hbuf + (size_t)(t & 1) * 8192);
        for (int idx = tid; idx < 2048; idx += 384) {
            int b = idx >> 8, k4 = idx & 255;
            float4 v = __ldcg((const float4*)(hsrc + (size_t)b*1024) + k4);
            *(float4*)&hs[b*HSTR + k4*4] = v;
        }
        // prefetch xg gates (hidden under the dot)
        float xr = 0.f, xz = 0.f, xn = 0.f;
        if (tid < 64) {
            const float* xb = xgbase + (size_t)t * 3072;
            xr = __ldg(xb);
            xz = __ldg(xb + 1024);
            xn = __ldg(xb + 2048);
        }
        __syncthreads();

        float a0=0.f, a1=0.f, a2=0.f, a3=0.f;
#pragma unroll 8
        for (int k = 0; k < 128; k++) {
            float4 w4 = wp[k];
            float4 h4 = hp[k];
            a0 = fmaf(w4.x, h4.x, a0);
            a1 = fmaf(w4.y, h4.y, a1);
            a2 = fmaf(w4.z, h4.z, a2);
            a3 = fmaf(w4.w, h4.w, a3);
        }
        part[tid] = (a0+a1) + (a2+a3);
        __syncthreads();

        if (tid < 64) {
            float hr = part[tid]       + part[192 + tid] + bhr;
            float hz = part[64 + tid]  + part[256 + tid] + bhz;
            float hn = part[128 + tid] + part[320 + tid] + bhn;
            float rg = 1.f/(1.f + expf(-(xr + hr)));
            float zg = 1.f/(1.f + expf(-(xz + hz)));
            float ng = tanhf(xn + rg*hn);
            float hnew = (1.f - zg)*ng + zg*hs[bg*HSTR + jg];
            hbuf[(size_t)((t+1) & 1)*8192 + bg*1024 + jg] = hnew;
            ys[(size_t)(bg*512 + t)*1024 + jg] = hnew;
            if (t == 511) hT[bg*1024 + jg] = hnew;
        }
        __threadfence();
        __syncthreads();
        if (tid == 0) {
            atomicAdd(&g_bar, 1u);
            unsigned want = (unsigned)(t + 1) * gridDim.x;
            while (*((volatile unsigned*)&g_bar) < want) { }
            __threadfence();
        }
        __syncthreads();
    }
}

// out[b,c,p] = sum_k W[c,k]*X[b,k,p] + bias[c] + add ; addmode1 = emb2(ys)
__global__ void __launch_bounds__(256, 2) pconv_kernel(
    const float* __restrict__ X, const float* __restrict__ W,
    const float* __restrict__ bias, const float* __restrict__ add,
    float* __restrict__ out, int npos, int addmode)
{
    __shared__ float Wt[32][132];
    __shared__ float Xs[32][132];
    const int tid = threadIdx.x;
    const int b = blockIdx.y, p0 = blockIdx.x * 128;
    const int ty = tid >> 4, tx = tid & 15;
    const float* Xb = X + (size_t)b * 128 * npos;
    float acc[8][8];
#pragma unroll
    for (int i = 0; i < 8; i++)
#pragma unroll
        for (int j = 0; j < 8; j++) acc[i][j] = 0.f;
    for (int k0 = 0; k0 < 128; k0 += 32) {
        __syncthreads();
#pragma unroll
        for (int l = 0; l < 4; l++) {
            int idx = tid + l*256;
            int c = idx >> 3, k4 = idx & 7;
            float4 v = *(const float4*)(W + c*128 + k0 + k4*4);
            Wt[k4*4+0][c]=v.x; Wt[k4*4+1][c]=v.y; Wt[k4*4+2][c]=v.z; Wt[k4*4+3][c]=v.w;
        }
#pragma unroll
        for (int l = 0; l < 4; l++) {
            int idx = tid + l*256;
            int k = idx >> 5, p4 = idx & 31;
            float4 v = *(const float4*)(Xb + (size_t)(k0+k)*npos + p0 + p4*4);
            *(float4*)&Xs[k][p4*4] = v;
        }
        __syncthreads();
#pragma unroll
        for (int k = 0; k < 32; k++) {
            float ar[8], br[8];
            *(float4*)(ar)   = *(const float4*)&Wt[k][ty*8];
            *(float4*)(ar+4) = *(const float4*)&Wt[k][ty*8+4];
            *(float4*)(br)   = *(const float4*)&Xs[k][tx*8];
            *(float4*)(br+4) = *(const float4*)&Xs[k][tx*8+4];
#pragma unroll
            for (int i = 0; i < 8; i++)
#pragma unroll
                for (int j = 0; j < 8; j++)
                    acc[i][j] = fmaf(ar[i], br[j], acc[i][j]);
        }
    }
#pragma unroll
    for (int i = 0; i < 8; i++) {
        int c = ty*8 + i;
        float bv = bias[c];
#pragma unroll
        for (int j = 0; j < 8; j++) {
            int p = p0 + tx*8 + j;
            float v = acc[i][j] + bv;
            if (addmode == 1) {
                int t = p >> 3, f = p & 7;
                v += add[(size_t)(b*512 + t)*1024 + f*128 + c];
            } else {
                v += add[((size_t)b*128 + c)*npos + p];
            }
            out[((size_t)b*128 + c)*npos + p] = v;
        }
    }
}

// Fused transposed conv (k=3,s=2,p=1,op=1) + bias + ReLU.
// Even out: y[..,2fi]   = relu(b + sum_k w[c,k,1]*X[k,p])
// Odd  out: y[..,2fi+1] = relu(b + sum_k w[c,k,0]*X[k,p] + w[c,k,2]*X[k,p+1])
// (tap-2 zero at fi == f_in-1). Tile: 64 c x 128 p, 256 thr, 4x8x2 per thread.
__global__ void __launch_bounds__(256, 2) convt_fused_kernel(
    const float* __restrict__ X, const float* __restrict__ wt,
    const float* __restrict__ bias, float* __restrict__ out,
    int npos, int fsh)
{
    __shared__ float Wt0[32][68];
    __shared__ float Wt1[32][68];
    __shared__ float Wt2[32][68];
    __shared__ float Xs[32][132];
    const int tid = threadIdx.x;
    const int b  = blockIdx.y;
    const int c0 = (blockIdx.x & 1) * 64;
    const int p0 = (blockIdx.x >> 1) * 128;
    const int tx = tid & 15, ty = tid >> 4;
    const int fmask = (1 << fsh) - 1;
    const float* Xb = X + (size_t)b * 128 * npos;
    const float m7 = (((p0 + tx*8 + 7) & fmask) == fmask) ? 0.f : 1.f;

    float accE[4][8], accO[4][8];
#pragma unroll
    for (int i = 0; i < 4; i++)
#pragma unroll
        for (int j = 0; j < 8; j++) { accE[i][j] = 0.f; accO[i][j] = 0.f; }

    for (int k0 = 0; k0 < 128; k0 += 32) {
        __syncthreads();
        for (int idx = tid; idx < 2048; idx += 256) {
            int cc = idx >> 5, kk = idx & 31;
            const float* wrow = wt + ((size_t)(c0+cc)*128 + k0+kk)*3;
            Wt0[kk][cc] = wrow[0];
            Wt1[kk][cc] = wrow[1];
            Wt2[kk][cc] = wrow[2];
        }
        for (int idx = tid; idx < 1024; idx += 256) {
            int kk = idx >> 5, p4 = idx & 31;
            float4 v = *(const float4*)(Xb + (size_t)(k0+kk)*npos + p0 + p4*4);
            *(float4*)&Xs[kk][p4*4] = v;
        }
        if (tid < 32) {
            float v = 0.f;
            if (p0 + 128 < npos) v = Xb[(size_t)(k0+tid)*npos + p0 + 128];
            Xs[tid][128] = v;
        }
        __syncthreads();
#pragma unroll
        for (int k = 0; k < 32; k++) {
            float w0a[4], w1a[4], w2a[4], x[9];
            *(float4*)w0a = *(const float4*)&Wt0[k][ty*4];
            *(float4*)w1a = *(const float4*)&Wt1[k][ty*4];
            *(float4*)w2a = *(const float4*)&Wt2[k][ty*4];
            *(float4*)(x)   = *(const float4*)&Xs[k][tx*8];
            *(float4*)(x+4) = *(const float4*)&Xs[k][tx*8+4];
            x[8] = Xs[k][tx*8+8] * m7;
#pragma unroll
            for (int i = 0; i < 4; i++) {
#pragma unroll
                for (int j = 0; j < 8; j++) {
                    accE[i][j] = fmaf(w1a[i], x[j],   accE[i][j]);
                    accO[i][j] = fmaf(w0a[i], x[j],   accO[i][j]);
                    accO[i][j] = fmaf(w2a[i], x[j+1], accO[i][j]);
                }
            }
        }
    }
#pragma unroll
    for (int i = 0; i < 4; i++) {
        int c = c0 + ty*4 + i;
        float bv = bias[c];
#pragma unroll
        for (int j = 0; j < 8; j++) {
            int p = p0 + tx*8 + j;
            int t = p >> fsh, fi = p & fmask;
            float ve = accE[i][j] + bv; ve = (ve > 0.f) ? ve : 0.f;
            float vo = accO[i][j] + bv; vo = (vo > 0.f) ? vo : 0.f;
            float2 v2; v2.x = ve; v2.y = vo;
            *(float2*)&out[((((size_t)b*128 + c)*512 + t) << (fsh+1)) + 2*fi] = v2;
        }
    }
}

// final 1x3 conv over f (C=128 -> 1) + sigmoid, one block per (b,t)
__global__ void __launch_bounds__(128) mask_kernel(
    const float* __restrict__ pre, const float* __restrict__ w0o,
    const float* __restrict__ b0o, float* __restrict__ out)
{
    __shared__ float ps[128][68];
    __shared__ float ws[384];
    __shared__ float red[128];
    const int bt = blockIdx.x;
    const int b = bt >> 9, t = bt & 511;
    const int tid = threadIdx.x;
    for (int idx = tid; idx < 2048; idx += 128) {   // 128 c x 16 float4
        int c = idx >> 4, q = idx & 15;
        float4 v = *(const float4*)(pre + (((size_t)b*128 + c)*512 + t)*64 + q*4);
        *(float4*)&ps[c][q*4] = v;
    }
    for (int i = tid; i < 384; i += 128) ws[i] = w0o[i];
    __syncthreads();
    const int f = tid & 63, half = tid >> 6;
    float acc = 0.f;
#pragma unroll 4
    for (int ci = half*64; ci < half*64 + 64; ci++) {
        float xm1 = (f > 0)  ? ps[ci][f-1] : 0.f;
        float x0  = ps[ci][f];
        float xp1 = (f < 63) ? ps[ci][f+1] : 0.f;
        acc += ws[ci*3]*xm1 + ws[ci*3+1]*x0 + ws[ci*3+2]*xp1;
    }
    red[tid] = acc;
    __syncthreads();
    if (tid < 64)
        out[(size_t)(b*512 + t)*64 + tid] =
            1.f/(1.f + expf(-(red[tid] + red[tid+64] + b0o[0])));
}

extern "C" void kernel_launch(void* const* d_in, const int* in_sizes, int n_in,
                              void* d_out, int out_size)
{
    const float* emb  = (const float*)d_in[0];
    const float* e3   = (const float*)d_in[1];
    const float* e2   = (const float*)d_in[2];
    const float* e1   = (const float*)d_in[3];
    const float* e0   = (const float*)d_in[4];
    const float* herb = (const float*)d_in[5];
    const float* Wih  = (const float*)d_in[6];
    const float* Whh  = (const float*)d_in[7];
    const float* bih  = (const float*)d_in[8];
    const float* bhh  = (const float*)d_in[9];
    const float* w3p  = (const float*)d_in[10];
    const float* b3p  = (const float*)d_in[11];
    const float* w2p  = (const float*)d_in[12];
    const float* b2p  = (const float*)d_in[13];
    const float* w1p  = (const float*)d_in[14];
    const float* b1p  = (const float*)d_in[15];
    const float* w0p  = (const float*)d_in[16];
    const float* b0p  = (const float*)d_in[17];
    const float* wt3  = (const float*)d_in[18];
    const float* bt3  = (const float*)d_in[19];
    const float* wt2  = (const float*)d_in[20];
    const float* bt2  = (const float*)d_in[21];
    const float* wt1  = (const float*)d_in[22];
    const float* bt1  = (const float*)d_in[23];
    const float* w0o  = (const float*)d_in[24];
    const float* b0o  = (const float*)d_in[25];
    float* out = (float*)d_out;

    float *xg, *ys, *hbuf, *pre, *dec3, *dec2, *dec1;
    cudaGetSymbolAddress((void**)&xg,   d_xg);
    cudaGetSymbolAddress((void**)&ys,   d_ys);
    cudaGetSymbolAddress((void**)&hbuf, d_hbuf);
    cudaGetSymbolAddress((void**)&pre,  d_pre);
    cudaGetSymbolAddress((void**)&dec3, d_dec3);
    cudaGetSymbolAddress((void**)&dec2, d_dec2);
    cudaGetSymbolAddress((void**)&dec1, d_dec1);

    static int smem_set = 0;
    if (!smem_set) {
        cudaFuncSetAttribute(gru_scan_kernel,
            cudaFuncAttributeMaxDynamicSharedMemorySize, GRU_SMEM);
        smem_set = 1;
    }

    reset_bar_kernel<<<1, 1>>>();
    xg_gemm_kernel<<<dim3(24, 32), 256>>>(emb, Wih, bih, xg);
    gru_scan_kernel<<<128, 384, GRU_SMEM>>>(Whh, bhh, herb, hbuf, ys, xg,
                                            out + 262144);
    // stage 3: f 8 -> 16
    pconv_kernel<<<dim3(32, 8), 256>>>(e3, w3p, b3p, ys, pre, 4096, 1);
    convt_fused_kernel<<<dim3(64, 8), 256>>>(pre, wt3, bt3, dec3, 4096, 3);
    // stage 2: f 16 -> 32
    pconv_kernel<<<dim3(64, 8), 256>>>(e2, w2p, b2p, dec3, pre, 8192, 0);
    convt_fused_kernel<<<dim3(128, 8), 256>>>(pre, wt2, bt2, dec2, 8192, 4);
    // stage 1: f 32 -> 64
    pconv_kernel<<<dim3(128, 8), 256>>>(e1, w1p, b1p, dec2, pre, 16384, 0);
    convt_fused_kernel<<<dim3(256, 8), 256>>>(pre, wt1, bt1, dec1, 16384, 5);
    // stage 0: pconv + skip, then 1x3 conv + sigmoid
    pconv_kernel<<<dim3(256, 8), 256>>>(e0, w0p, b0p, dec1, pre, 32768, 0);
    mask_kernel<<<4096, 128>>>(pre, w0o, b0o, out);
}

// round 13
// speedup vs baseline: 1.3567x; 1.0228x over previous
#include <cuda_runtime.h>
#include <math.h>

#define WSTR 1048
#define HSTR 1028
#define GRU_SMEM ((24*WSTR + 8*HSTR + 384)*4)
#define FS_SMEM ((128*132 + 8448)*4)

__device__ float d_xg[12582912];    // (8,512,3072)
__device__ float d_ys[4194304];     // (8,512,1024)
__device__ float d_hbuf[2*8192];
__device__ float d_dec3[8388608];   // (8,128,512,16)
__device__ float d_dec2[16777216];  // (8,128,512,32)
__device__ float d_dec1[33554432];  // (8,128,512,64)
__device__ unsigned g_bar;
__device__ unsigned d_done[4];      // xg chunk counters (128 t each)

__global__ void reset_bar_kernel() {
    g_bar = 0u;
    d_done[0] = d_done[1] = d_done[2] = d_done[3] = 0u;
}

// C[m,n] = sum_k A[m,k]*Bm[n,k] + bias[n];  A:(4096,1024) Bm:(3072,1024)
// blockIdx.y = mtile; t-chunk = mtile & 3; bumps d_done[chunk] when finished.
__global__ void __launch_bounds__(256) xg_gemm_kernel(
    const float* __restrict__ A, const float* __restrict__ Bm,
    const float* __restrict__ bias, float* __restrict__ C)
{
    __shared__ float As[8][128];
    __shared__ float Bs[8][128];
    const int tid = threadIdx.x;
    const int bm = blockIdx.y * 128, bn = blockIdx.x * 128;
    const int lr = tid >> 1, lk = (tid & 1) * 4;
    const float* Ap = A  + (size_t)(bm + lr) * 1024 + lk;
    const float* Bp = Bm + (size_t)(bn + lr) * 1024 + lk;
    const int ty = tid >> 4, tx = tid & 15;
    float acc[8][8];
#pragma unroll
    for (int i = 0; i < 8; i++)
#pragma unroll
        for (int j = 0; j < 8; j++) acc[i][j] = 0.f;

    float4 a4 = *(const float4*)(Ap);
    float4 b4 = *(const float4*)(Bp);
    for (int k0 = 0; k0 < 1024; k0 += 8) {
        __syncthreads();
        As[lk+0][lr]=a4.x; As[lk+1][lr]=a4.y; As[lk+2][lr]=a4.z; As[lk+3][lr]=a4.w;
        Bs[lk+0][lr]=b4.x; Bs[lk+1][lr]=b4.y; Bs[lk+2][lr]=b4.z; Bs[lk+3][lr]=b4.w;
        __syncthreads();
        if (k0 + 8 < 1024) {
            a4 = *(const float4*)(Ap + k0 + 8);
            b4 = *(const float4*)(Bp + k0 + 8);
        }
#pragma unroll
        for (int k = 0; k < 8; k++) {
            float ar[8], br[8];
            *(float4*)(ar)   = *(const float4*)&As[k][ty*8];
            *(float4*)(ar+4) = *(const float4*)&As[k][ty*8+4];
            *(float4*)(br)   = *(const float4*)&Bs[k][tx*8];
            *(float4*)(br+4) = *(const float4*)&Bs[k][tx*8+4];
#pragma unroll
            for (int i = 0; i < 8; i++)
#pragma unroll
                for (int j = 0; j < 8; j++)
                    acc[i][j] = fmaf(ar[i], br[j], acc[i][j]);
        }
    }
#pragma unroll
    for (int i = 0; i < 8; i++) {
        int m = bm + ty*8 + i;
#pragma unroll
        for (int j = 0; j < 8; j++) {
            int n = bn + tx*8 + j;
            C[(size_t)m*3072 + n] = acc[i][j] + bias[n];
        }
    }
    __threadfence();
    __syncthreads();
    if (tid == 0) atomicAdd(&d_done[blockIdx.y & 3], 1u);
}

// Persistent GRU scan: 128 blocks x 384 thr, block owns 8 hidden units.
// Split-K x2. Waits per-128-step chunk for xg producer (runs concurrently).
__global__ void __launch_bounds__(384) gru_scan_kernel(
    const float* __restrict__ Whh, const float* __restrict__ bhh,
    const float* __restrict__ h0, float* __restrict__ hbuf,
    float* __restrict__ ys, const float* __restrict__ xg,
    float* __restrict__ hT)
{
    extern __shared__ float sm[];
    float* Ws   = sm;
    float* hs   = sm + 24*WSTR;
    float* part = hs + 8*HSTR;
    const int tid = threadIdx.x;
    const int j0 = blockIdx.x * 8;

    for (int idx = tid; idx < 24*256; idx += 384) {
        int lrr = idx >> 8, k4 = idx & 255;
        int grow = ((lrr >> 3) << 10) + j0 + (lrr & 7);
        float4 v = *(const float4*)(Whh + (size_t)grow*1024 + k4*4);
        *(float4*)&Ws[lrr*WSTR + k4*4] = v;
    }
    const int h2 = tid / 192;
    const int r  = tid % 192;
    const int lr = r >> 3;
    const int bb = r & 7;
    const float4* wp = (const float4*)(Ws + lr*WSTR + h2*512);
    const float4* hp = (const float4*)(hs + bb*HSTR + h2*512);

    float bhr = 0.f, bhz = 0.f, bhn = 0.f;
    const float* xgbase = 0;
    int jg = 0, bg = 0;
    if (tid < 64) {
        jg = j0 + (tid >> 3);
        bg = tid & 7;
        bhr = bhh[jg];
        bhz = bhh[1024 + jg];
        bhn = bhh[2048 + jg];
        xgbase = xg + (size_t)bg * 512 * 3072 + jg;
    }
    __syncthreads();

    for (int t = 0; t < 512; t++) {
        if ((t & 127) == 0) {           // wait for xg chunk
            if (tid == 0) {
                volatile unsigned* dp = (volatile unsigned*)&d_done[t >> 7];
                while (*dp < 192u) { }
                __threadfence();
            }
            __syncthreads();
        }
        const float* hsrc = (t == 0) ? h0 : (hbuf + (size_t)(t & 1) * 8192);
        for (int idx = tid; idx < 2048; idx += 384) {
            int b = idx >> 8, k4 = idx & 255;
            float4 v = __ldcg((const float4*)(hsrc + (size_t)b*1024) + k4);
            *(float4*)&hs[b*HSTR + k4*4] = v;
        }
        float xr = 0.f, xz = 0.f, xn = 0.f;
        if (tid < 64) {
            const float* xb = xgbase + (size_t)t * 3072;
            xr = __ldcg(xb);
            xz = __ldcg(xb + 1024);
            xn = __ldcg(xb + 2048);
        }
        __syncthreads();

        float a0=0.f, a1=0.f, a2=0.f, a3=0.f;
#pragma unroll 8
        for (int k = 0; k < 128; k++) {
            float4 w4 = wp[k];
            float4 h4 = hp[k];
            a0 = fmaf(w4.x, h4.x, a0);
            a1 = fmaf(w4.y, h4.y, a1);
            a2 = fmaf(w4.z, h4.z, a2);
            a3 = fmaf(w4.w, h4.w, a3);
        }
        part[tid] = (a0+a1) + (a2+a3);
        __syncthreads();

        if (tid < 64) {
            float hr = part[tid]       + part[192 + tid] + bhr;
            float hz = part[64 + tid]  + part[256 + tid] + bhz;
            float hn = part[128 + tid] + part[320 + tid] + bhn;
            float rg = 1.f/(1.f + expf(-(xr + hr)));
            float zg = 1.f/(1.f + expf(-(xz + hz)));
            float ng = tanhf(xn + rg*hn);
            float hnew = (1.f - zg)*ng + zg*hs[bg*HSTR + jg];
            hbuf[(size_t)((t+1) & 1)*8192 + bg*1024 + jg] = hnew;
            ys[(size_t)(bg*512 + t)*1024 + jg] = hnew;
            if (t == 511) hT[bg*1024 + jg] = hnew;
        }
        __threadfence();
        __syncthreads();
        if (tid == 0) {
            atomicAdd(&g_bar, 1u);
            unsigned want = (unsigned)(t + 1) * gridDim.x;
            while (*((volatile unsigned*)&g_bar) < want) { }
            __threadfence();
        }
        __syncthreads();
    }
}

// ---------------------------------------------------------------------------
// Fused decoder stage: phase1 pconv(+skip) -> smem P[128][132];
// phase2 transposed conv (k=3,s=2,p=1,op=1) even+odd + bias + ReLU -> out.
// Tile: 128 c x 128 p per block. 256 threads.
// ---------------------------------------------------------------------------
__global__ void __launch_bounds__(256, 2) fused_stage_kernel(
    const float* __restrict__ X, const float* __restrict__ Wp,
    const float* __restrict__ bp, const float* __restrict__ add,
    const float* __restrict__ wt, const float* __restrict__ bt,
    float* __restrict__ out, int npos, int fsh, int addmode)
{
    extern __shared__ float smf[];
    float* P  = smf;             // 128 x 132
    float* S  = smf + 128*132;   // 8448 floats of staging
    float* Wt = S;               // phase1 [32][132]
    float* Xs = S + 4224;
    const int tid = threadIdx.x;
    const int b = blockIdx.y, p0 = blockIdx.x * 128;
    const int ty = tid >> 4, tx = tid & 15;
    const int fmask = (1 << fsh) - 1;
    const float* Xb = X + (size_t)b * 128 * npos;

    // ---------------- phase 1: pconv ----------------
    float acc[8][8];
#pragma unroll
    for (int i = 0; i < 8; i++)
#pragma unroll
        for (int j = 0; j < 8; j++) acc[i][j] = 0.f;
    for (int k0 = 0; k0 < 128; k0 += 32) {
        __syncthreads();
#pragma unroll
        for (int l = 0; l < 4; l++) {
            int idx = tid + l*256;
            int c = idx >> 3, k4 = idx & 7;
            float4 v = *(const float4*)(Wp + c*128 + k0 + k4*4);
            Wt[(k4*4+0)*132 + c]=v.x; Wt[(k4*4+1)*132 + c]=v.y;
            Wt[(k4*4+2)*132 + c]=v.z; Wt[(k4*4+3)*132 + c]=v.w;
        }
#pragma unroll
        for (int l = 0; l < 4; l++) {
            int idx = tid + l*256;
            int k = idx >> 5, p4 = idx & 31;
            float4 v = *(const float4*)(Xb + (size_t)(k0+k)*npos + p0 + p4*4);
            *(float4*)&Xs[k*132 + p4*4] = v;
        }
        __syncthreads();
#pragma unroll
        for (int k = 0; k < 32; k++) {
            float ar[8], br[8];
            *(float4*)(ar)   = *(const float4*)&Wt[k*132 + ty*8];
            *(float4*)(ar+4) = *(const float4*)&Wt[k*132 + ty*8+4];
            *(float4*)(br)   = *(const float4*)&Xs[k*132 + tx*8];
            *(float4*)(br+4) = *(const float4*)&Xs[k*132 + tx*8+4];
#pragma unroll
            for (int i = 0; i < 8; i++)
#pragma unroll
                for (int j = 0; j < 8; j++)
                    acc[i][j] = fmaf(ar[i], br[j], acc[i][j]);
        }
    }
#pragma unroll
    for (int i = 0; i < 8; i++) {
        int c = ty*8 + i;
        float bv = bp[c];
#pragma unroll
        for (int j = 0; j < 8; j++) {
            int pl = tx*8 + j;
            int p = p0 + pl;
            float v = acc[i][j] + bv;
            if (addmode == 1) {
                int t = p >> 3, f = p & 7;
                v += add[(size_t)(b*512 + t)*1024 + f*128 + c];
            } else {
                v += add[((size_t)b*128 + c)*npos + p];
            }
            P[c*132 + pl] = v;
        }
    }
    if (tid < 128) P[tid*132 + 128] = 0.f;   // guard column for p+1 tap

    // ---------------- phase 2: transposed conv ----------------
    const float m7 = (((p0 + tx*8 + 7) & fmask) == fmask) ? 0.f : 1.f;
    float* W0 = S;
    float* W1 = S + 2176;
    float* W2 = S + 4352;
    for (int ch = 0; ch < 2; ch++) {
        const int c0 = ch * 64;
        float accE[4][8], accO[4][8];
#pragma unroll
        for (int i = 0; i < 4; i++)
#pragma unroll
            for (int j = 0; j < 8; j++) { accE[i][j] = 0.f; accO[i][j] = 0.f; }
        for (int k0 = 0; k0 < 128; k0 += 32) {
            __syncthreads();
            for (int idx = tid; idx < 2048; idx += 256) {
                int cc = idx >> 5, kk = idx & 31;
                const float* wrow = wt + ((size_t)(c0+cc)*128 + k0+kk)*3;
                W0[kk*68 + cc] = wrow[0];
                W1[kk*68 + cc] = wrow[1];
                W2[kk*68 + cc] = wrow[2];
            }
            __syncthreads();
#pragma unroll
            for (int k = 0; k < 32; k++) {
                float w0a[4], w1a[4], w2a[4], x[9];
                *(float4*)w0a = *(const float4*)&W0[k*68 + ty*4];
                *(float4*)w1a = *(const float4*)&W1[k*68 + ty*4];
                *(float4*)w2a = *(const float4*)&W2[k*68 + ty*4];
                const float* pr = &P[(k0+k)*132 + tx*8];
                *(float4*)(x)   = *(const float4*)(pr);
                *(float4*)(x+4) = *(const float4*)(pr+4);
                x[8] = pr[8] * m7;
#pragma unroll
                for (int i = 0; i < 4; i++) {
#pragma unroll
                    for (int j = 0; j < 8; j++) {
                        accE[i][j] = fmaf(w1a[i], x[j],   accE[i][j]);
                        accO[i][j] = fmaf(w0a[i], x[j],   accO[i][j]);
                        accO[i][j] = fmaf(w2a[i], x[j+1], accO[i][j]);
                    }
                }
            }
        }
#pragma unroll
        for (int i = 0; i < 4; i++) {
            int c = c0 + ty*4 + i;
            float bv = bt[c];
#pragma unroll
            for (int j = 0; j < 8; j++) {
                int p = p0 + tx*8 + j;
                int t = p >> fsh, fi = p & fmask;
                float ve = accE[i][j] + bv; ve = (ve > 0.f) ? ve : 0.f;
                float vo = accO[i][j] + bv; vo = (vo > 0.f) ? vo : 0.f;
                float2 v2; v2.x = ve; v2.y = vo;
                *(float2*)&out[((((size_t)b*128 + c)*512 + t) << (fsh+1)) + 2*fi] = v2;
            }
        }
    }
}

// ---------------------------------------------------------------------------
// Fused stage 0: phase1 pconv(e0)+skip(dec1) -> smem; phase2 1x3 conv over f
// (128 ch -> 1) + sigmoid. Tile = 128 c x 128 p (2 t x 64 f). npos = 32768.
// ---------------------------------------------------------------------------
__global__ void __launch_bounds__(256, 2) fused_mask_kernel(
    const float* __restrict__ X, const float* __restrict__ Wp,
    const float* __restrict__ bp, const float* __restrict__ add,
    const float* __restrict__ w0o, const float* __restrict__ b0o,
    float* __restrict__ out)
{
    extern __shared__ float smf[];
    float* P  = smf;
    float* S  = smf + 128*132;
    float* Wt = S;
    float* Xs = S + 4224;
    const int tid = threadIdx.x;
    const int b = blockIdx.y, p0 = blockIdx.x * 128;
    const int ty = tid >> 4, tx = tid & 15;
    const int npos = 32768;
    const float* Xb = X + (size_t)b * 128 * npos;

    float acc[8][8];
#pragma unroll
    for (int i = 0; i < 8; i++)
#pragma unroll
        for (int j = 0; j < 8; j++) acc[i][j] = 0.f;
    for (int k0 = 0; k0 < 128; k0 += 32) {
        __syncthreads();
#pragma unroll
        for (int l = 0; l < 4; l++) {
            int idx = tid + l*256;
            int c = idx >> 3, k4 = idx & 7;
            float4 v = *(const float4*)(Wp + c*128 + k0 + k4*4);
            Wt[(k4*4+0)*132 + c]=v.x; Wt[(k4*4+1)*132 + c]=v.y;
            Wt[(k4*4+2)*132 + c]=v.z; Wt[(k4*4+3)*132 + c]=v.w;
        }
#pragma unroll
        for (int l = 0; l < 4; l++) {
            int idx = tid + l*256;
            int k = idx >> 5, p4 = idx & 31;
            float4 v = *(const float4*)(Xb + (size_t)(k0+k)*npos + p0 + p4*4);
            *(float4*)&Xs[k*132 + p4*4] = v;
        }
        __syncthreads();
#pragma unroll
        for (int k = 0; k < 32; k++) {
            float ar[8], br[8];
            *(float4*)(ar)   = *(const float4*)&Wt[k*132 + ty*8];
            *(float4*)(ar+4) = *(const float4*)&Wt[k*132 + ty*8+4];
            *(float4*)(br)   = *(const float4*)&Xs[k*132 + tx*8];
            *(float4*)(br+4) = *(const float4*)&Xs[k*132 + tx*8+4];
#pragma unroll
            for (int i = 0; i < 8; i++)
#pragma unroll
                for (int j = 0; j < 8; j++)
                    acc[i][j] = fmaf(ar[i], br[j], acc[i][j]);
        }
    }
#pragma unroll
    for (int i = 0; i < 8; i++) {
        int c = ty*8 + i;
        float bv = bp[c];
#pragma unroll
        for (int j = 0; j < 8; j++) {
            int pl = tx*8 + j;
            int p = p0 + pl;
            P[c*132 + pl] = acc[i][j] + bv + add[((size_t)b*128 + c)*npos + p];
        }
    }
    __syncthreads();

    // phase 2: mask. S reused: ws[384] + red[256]
    float* ws  = S;
    float* red = S + 384;
    for (int i = tid; i < 384; i += 256) ws[i] = w0o[i];
    __syncthreads();
    const int o = tid & 127, half = tid >> 7;
    const int f = o & 63, tl = o >> 6;
    const int pl = tl*64 + f;
    float a = 0.f;
#pragma unroll 4
    for (int ci = half*64; ci < half*64 + 64; ci++) {
        float xm1 = (f > 0)  ? P[ci*132 + pl - 1] : 0.f;
        float x0  = P[ci*132 + pl];
        float xp1 = (f < 63) ? P[ci*132 + pl + 1] : 0.f;
        a += ws[ci*3]*xm1 + ws[ci*3+1]*x0 + ws[ci*3+2]*xp1;
    }
    red[tid] = a;
    __syncthreads();
    if (tid < 128) {
        int p = p0 + tid;
        out[(size_t)b*32768 + p] =
            1.f/(1.f + expf(-(red[tid] + red[tid+128] + b0o[0])));
    }
}

extern "C" void kernel_launch(void* const* d_in, const int* in_sizes, int n_in,
                              void* d_out, int out_size)
{
    const float* emb  = (const float*)d_in[0];
    const float* e3   = (const float*)d_in[1];
    const float* e2   = (const float*)d_in[2];
    const float* e1   = (const float*)d_in[3];
    const float* e0   = (const float*)d_in[4];
    const float* herb = (const float*)d_in[5];
    const float* Wih  = (const float*)d_in[6];
    const float* Whh  = (const float*)d_in[7];
    const float* bih  = (const float*)d_in[8];
    const float* bhh  = (const float*)d_in[9];
    const float* w3p  = (const float*)d_in[10];
    const float* b3p  = (const float*)d_in[11];
    const float* w2p  = (const float*)d_in[12];
    const float* b2p  = (const float*)d_in[13];
    const float* w1p  = (const float*)d_in[14];
    const float* b1p  = (const float*)d_in[15];
    const float* w0p  = (const float*)d_in[16];
    const float* b0p  = (const float*)d_in[17];
    const float* wt3  = (const float*)d_in[18];
    const float* bt3  = (const float*)d_in[19];
    const float* wt2  = (const float*)d_in[20];
    const float* bt2  = (const float*)d_in[21];
    const float* wt1  = (const float*)d_in[22];
    const float* bt1  = (const float*)d_in[23];
    const float* w0o  = (const float*)d_in[24];
    const float* b0o  = (const float*)d_in[25];
    float* out = (float*)d_out;

    float *xg, *ys, *hbuf, *dec3, *dec2, *dec1;
    cudaGetSymbolAddress((void**)&xg,   d_xg);
    cudaGetSymbolAddress((void**)&ys,   d_ys);
    cudaGetSymbolAddress((void**)&hbuf, d_hbuf);
    cudaGetSymbolAddress((void**)&dec3, d_dec3);
    cudaGetSymbolAddress((void**)&dec2, d_dec2);
    cudaGetSymbolAddress((void**)&dec1, d_dec1);

    static cudaStream_t s2;
    static cudaEvent_t evA, evB;
    static int init_done = 0;
    if (!init_done) {
        cudaFuncSetAttribute(gru_scan_kernel,
            cudaFuncAttributeMaxDynamicSharedMemorySize, GRU_SMEM);
        cudaFuncSetAttribute(fused_stage_kernel,
            cudaFuncAttributeMaxDynamicSharedMemorySize, FS_SMEM);
        cudaFuncSetAttribute(fused_mask_kernel,
            cudaFuncAttributeMaxDynamicSharedMemorySize, FS_SMEM);
        cudaStreamCreateWithFlags(&s2, cudaStreamNonBlocking);
        cudaEventCreateWithFlags(&evA, cudaEventDisableTiming);
        cudaEventCreateWithFlags(&evB, cudaEventDisableTiming);
        init_done = 1;
    }

    reset_bar_kernel<<<1, 1>>>();

    // fork: xg producer on s2, concurrent with the persistent GRU scan
    cudaEventRecord(evA, 0);
    cudaStreamWaitEvent(s2, evA, 0);
    xg_gemm_kernel<<<dim3(24, 32), 256, 0, s2>>>(emb, Wih, bih, xg);
    cudaEventRecord(evB, s2);

    gru_scan_kernel<<<128, 384, GRU_SMEM>>>(Whh, bhh, herb, hbuf, ys, xg,
                                            out + 262144);
    cudaStreamWaitEvent(0, evB, 0);   // join before decoder

    // decoder: fused pconv+convt per stage
    fused_stage_kernel<<<dim3(32, 8),  256, FS_SMEM>>>(e3, w3p, b3p, ys,
                                                       wt3, bt3, dec3, 4096, 3, 1);
    fused_stage_kernel<<<dim3(64, 8),  256, FS_SMEM>>>(e2, w2p, b2p, dec3,
                                                       wt2, bt2, dec2, 8192, 4, 0);
    fused_stage_kernel<<<dim3(128, 8), 256, FS_SMEM>>>(e1, w1p, b1p, dec2,
                                                       wt1, bt1, dec1, 16384, 5, 0);
    // stage 0: fused pconv + 1x3 conv + sigmoid
    fused_mask_kernel<<<dim3(256, 8), 256, FS_SMEM>>>(e0, w0p, b0p, dec1,
                                                      w0o, b0o, out);
}